// round 14
// baseline (speedup 1.0000x reference)
#include <cuda_runtime.h>
#include <cuda_fp16.h>
#include <cstdint>

// Problem constants
#define BATCH 2
#define SEQ   2048
#define DMODEL 1024
#define NHEADS 16
#define DK    64
#define NTOK  (BATCH*SEQ)          // 4096
#define BH    (BATCH*NHEADS)       // 32

// ---------------------------------------------------------------------------
// Scratch (device globals; no runtime allocation allowed)
// fp16 2-term scheme: A-side operands keep (hi, lo); B-side operands keep hi
// only.  C = Ah*Bh + Al*Bh; dropped A*Bl term ~2^-12 relative (<< 1e-3).
// ---------------------------------------------------------------------------
__device__ __half g_inH[3][NTOK*DMODEL];    // split inputs (A-side: hi)
__device__ __half g_inL[3][NTOK*DMODEL];    //                      (lo)
__device__ __half g_WH[4][DMODEL*DMODEL];   // weights (B-side: hi only)
__device__ __half g_QH[BH*SEQ*DK], g_QL[BH*SEQ*DK];   // Q: A-side hi/lo
__device__ __half g_KH[BH*SEQ*DK];                    // K: B-side hi only
__device__ float  g_V [BH*SEQ*DK];                    // fp32 [b,h,s,d]
__device__ __half g_VTH[BH*DK*SEQ];                   // V^T: B-side hi only
__device__ __half g_ctxH[NTOK*DMODEL], g_ctxL[NTOK*DMODEL]; // ctx: A-side
__device__ float g_tmp[NTOK*DMODEL];         // pre-LN
__device__ float g_meanV[BH*DK];
__device__ int   g_fm[NTOK];                 // 1 if row has NO unmasked future key

// ---------------------------------------------------------------------------
// mma.sync m16n8k16 fp16 + ldmatrix (tcgen05 rejected by this ptxas target)
// ---------------------------------------------------------------------------
__device__ __forceinline__ void mma16816(float* c, const uint32_t* a,
                                         const uint32_t* b) {
    asm volatile(
        "mma.sync.aligned.m16n8k16.row.col.f32.f16.f16.f32 "
        "{%0,%1,%2,%3}, {%4,%5,%6,%7}, {%8,%9}, {%0,%1,%2,%3};"
        : "+f"(c[0]), "+f"(c[1]), "+f"(c[2]), "+f"(c[3])
        : "r"(a[0]), "r"(a[1]), "r"(a[2]), "r"(a[3]), "r"(b[0]), "r"(b[1]));
}
__device__ __forceinline__ void ldsm_x4(uint32_t* r, uint32_t addr) {
    asm volatile("ldmatrix.sync.aligned.m8n8.x4.shared.b16 {%0,%1,%2,%3}, [%4];"
                 : "=r"(r[0]), "=r"(r[1]), "=r"(r[2]), "=r"(r[3]) : "r"(addr));
}
__device__ __forceinline__ void ldsm_x2(uint32_t* r, uint32_t addr) {
    asm volatile("ldmatrix.sync.aligned.m8n8.x2.shared.b16 {%0,%1}, [%2];"
                 : "=r"(r[0]), "=r"(r[1]) : "r"(addr));
}

__device__ __forceinline__ uint32_t pack_h2(float a, float b) {
    __half2 t = __floats2half2_rn(a, b);
    return *(uint32_t*)&t;
}
__device__ __forceinline__ uint32_t phbits(__half a, __half b) {
    uint16_t ab = *(uint16_t*)&a, bb = *(uint16_t*)&b;
    return (uint32_t)ab | ((uint32_t)bb << 16);
}
__device__ __forceinline__ void cpasync16(uint32_t dst, const void* src) {
    asm volatile("cp.async.cg.shared.global [%0], [%1], 16;"
                 :: "r"(dst), "l"(src));
}
#define CP_COMMIT() asm volatile("cp.async.commit_group;" ::: "memory")
#define CP_WAIT0()  asm volatile("cp.async.wait_group 0;" ::: "memory")

// ---------------------------------------------------------------------------
// Split kernels: fp32 -> fp16 (hi, lo) for A-side; hi-only for B-side weights
// ---------------------------------------------------------------------------
struct SplitJobs {
    const float4* x[4];
    uint2* hi[4];
    uint2* lo[4];
};

__global__ void __launch_bounds__(256) split_multi_kernel(SplitJobs jb)
{
    const int t = blockIdx.y;
    const int i = blockIdx.x * 256 + threadIdx.x;
    float4 v = jb.x[t][i];
    __half h0 = __float2half_rn(v.x), h1 = __float2half_rn(v.y);
    __half h2 = __float2half_rn(v.z), h3 = __float2half_rn(v.w);
    jb.hi[t][i] = make_uint2(phbits(h0, h1), phbits(h2, h3));
    jb.lo[t][i] = make_uint2(
        pack_h2(v.x - __half2float(h0), v.y - __half2float(h1)),
        pack_h2(v.z - __half2float(h2), v.w - __half2float(h3)));
}

__global__ void __launch_bounds__(256) split_hi_kernel(SplitJobs jb)
{
    const int t = blockIdx.y;
    const int i = blockIdx.x * 256 + threadIdx.x;
    float4 v = jb.x[t][i];
    jb.hi[t][i] = make_uint2(
        pack_h2(v.x, v.y), pack_h2(v.z, v.w));
}

// ---------------------------------------------------------------------------
// GEMM body: C[m,n] = sum_k A[m,k]*W[n,k], A hi/lo fp16, W hi fp16.
// 2 terms: Ah*Wh + Al*Wh, fp32 accumulate.
// 128x128 CTA tile, 256 threads, k-chunk 32, cp.async double-buffered,
// ldmatrix fragment loads.
// ---------------------------------------------------------------------------
#define KC 32
#define SROW 20                // uint32 words per row (16 data words + 4 pad)
#define ARRW (128*SROW)        // 2560 words per array
#define GBUFW (3*ARRW)         // words per buffer (AH, AL, WH)
#define G_SMEM (2*GBUFW*4)     // 61440 bytes

__device__ __forceinline__ void gemm_body(
    const __half* __restrict__ Ah, const __half* __restrict__ Al,
    const __half* __restrict__ Wh,
    const float* __restrict__ resid, float* __restrict__ outF,
    __half* __restrict__ outH, __half* __restrict__ outL,
    int mode, uint32_t sb)
{
    const int tid  = threadIdx.x;
    const int wid  = tid >> 5;
    const int lane = tid & 31;
    const int bm = blockIdx.y * 128;
    const int bn = blockIdx.x * 128;

    const int mw = wid & 1;
    const int nw = wid >> 1;
    const int lr8 = lane & 7;
    const int lh  = (lane >> 3) & 1;
    const int lq  = lane >> 4;

    float acc[4][4][4];
#pragma unroll
    for (int mt = 0; mt < 4; mt++)
#pragma unroll
        for (int nt = 0; nt < 4; nt++)
#pragma unroll
            for (int i = 0; i < 4; i++) acc[mt][nt][i] = 0.f;

    auto prefetch = [&](int kt, int bsel) {
        const int kk = kt * KC;
        const uint32_t pb = sb + bsel * (GBUFW * 4);
#pragma unroll
        for (int it = 0; it < 2; it++) {
            const int idx = tid + it * 256;       // 0..511
            const int r  = idx >> 2;              // 0..127
            const int ch = idx & 3;               // 16B chunk
            const size_t ga = (size_t)(bm + r) * DMODEL + kk + ch * 8;
            const size_t gw = (size_t)(bn + r) * DMODEL + kk + ch * 8;
            const uint32_t so = (r * SROW + ch * 4) * 4;
            cpasync16(pb + so, Ah + ga);
            cpasync16(pb + ARRW * 4 + so, Al + ga);
            cpasync16(pb + 2 * ARRW * 4 + so, Wh + gw);
        }
    };

    int buf = 0;
    prefetch(0, 0);
    CP_COMMIT();

    for (int kt = 0; kt < DMODEL / KC; kt++) {
        CP_WAIT0();
        __syncthreads();
        if (kt + 1 < DMODEL / KC) prefetch(kt + 1, buf ^ 1);
        CP_COMMIT();

        const uint32_t bb = sb + buf * (GBUFW * 4);
#pragma unroll
        for (int ks = 0; ks < 2; ks++) {
            uint32_t bHf[4][2];
#pragma unroll
            for (int nt = 0; nt < 4; nt++) {
                const uint32_t aw = bb +
                    (2 * ARRW + (nw * 32 + nt * 8 + lr8) * SROW
                              + ks * 8 + lh * 4) * 4;
                ldsm_x2(bHf[nt], aw);
            }
#pragma unroll
            for (int mt = 0; mt < 4; mt++) {
                const uint32_t aw = bb +
                    ((mw * 64 + mt * 16 + lr8 + lh * 8) * SROW
                     + ks * 8 + lq * 4) * 4;
                uint32_t aH[4], aL[4];
                ldsm_x4(aH, aw);
                ldsm_x4(aL, aw + ARRW * 4);
#pragma unroll
                for (int nt = 0; nt < 4; nt++) {
                    mma16816(acc[mt][nt], aH, bHf[nt]);
                    mma16816(acc[mt][nt], aL, bHf[nt]);
                }
            }
        }
        __syncthreads();
        buf ^= 1;
    }

#pragma unroll
    for (int mt = 0; mt < 4; mt++) {
#pragma unroll
        for (int nt = 0; nt < 4; nt++) {
            const int m0 = bm + mw * 64 + mt * 16 + (lane >> 2);
            const int n  = bn + nw * 32 + nt * 8 + ((lane & 3) << 1);
#pragma unroll
            for (int half_ = 0; half_ < 2; half_++) {
                const int m = m0 + half_ * 8;
                const float c0 = acc[mt][nt][half_ * 2 + 0];
                const float c1 = acc[mt][nt][half_ * 2 + 1];
                if (mode == 1) {
                    const size_t off = (size_t)m * DMODEL + n;
                    float2 rs = *(const float2*)&resid[off];
                    *(float2*)&outF[off] = make_float2(c0 + rs.x, c1 + rs.y);
                } else {
                    const int b = m >> 11, s = m & 2047;
                    const int h = n >> 6, d0 = n & 63;
                    const size_t p =
                        ((size_t)(b * NHEADS + h) * SEQ + s) * DK + d0;
                    if (mode == 2) {
                        *(float2*)&outF[p] = make_float2(c0, c1);
                    } else {
                        __half h0 = __float2half_rn(c0);
                        __half h1 = __float2half_rn(c1);
                        *(uint32_t*)(outH + p) = phbits(h0, h1);
                        if (outL)
                            *(uint32_t*)(outL + p) =
                                pack_h2(c0 - __half2float(h0),
                                        c1 - __half2float(h1));
                    }
                }
            }
        }
    }
}

struct QKVPtrs {
    const __half *ah[3], *al[3], *wh[3];
};

__global__ void __launch_bounds__(256) qkv_gemm_kernel(
    QKVPtrs p, __half* qh, __half* ql, __half* kh, float* vout)
{
    extern __shared__ uint32_t gsm[];
    const uint32_t sb = (uint32_t)__cvta_generic_to_shared(gsm);
    const int z = blockIdx.z;
    __half* oh = (z == 0) ? qh : kh;
    __half* ol = (z == 0) ? ql : nullptr;   // K is B-side: hi only
    const int mode = (z == 2) ? 2 : 0;
    gemm_body(p.ah[z], p.al[z], p.wh[z], nullptr, vout, oh, ol, mode, sb);
}

__global__ void __launch_bounds__(256) outproj_gemm_kernel(
    const __half* __restrict__ ah, const __half* __restrict__ al,
    const __half* __restrict__ wh,
    const float* __restrict__ resid, float* __restrict__ outF)
{
    extern __shared__ uint32_t gsm[];
    const uint32_t sb = (uint32_t)__cvta_generic_to_shared(gsm);
    gemm_body(ah, al, wh, resid, outF, nullptr, nullptr, 1, sb);
}

// ---------------------------------------------------------------------------
// V transpose: [b,h,s,d] fp32 -> [b,h,d,s] fp16 hi (B-side of PV)
// ---------------------------------------------------------------------------
__global__ void __launch_bounds__(256) vsplitT_kernel(
    const float* __restrict__ V, __half* __restrict__ vth)
{
    __shared__ float tile[64][67];
    const int s0 = blockIdx.x * 64;
    const int bh = blockIdx.y;
    const float* vb = V + (size_t)bh * SEQ * DK;
    for (int idx = threadIdx.x; idx < 64 * 16; idx += 256) {
        const int r = idx >> 4, c4 = (idx & 15) << 2;
        float4 v = *(const float4*)&vb[(size_t)(s0 + r) * DK + c4];
        tile[r][c4] = v.x; tile[r][c4+1] = v.y;
        tile[r][c4+2] = v.z; tile[r][c4+3] = v.w;
    }
    __syncthreads();
    for (int idx = threadIdx.x; idx < 64 * 32; idx += 256) {
        const int d = idx >> 5, sp = idx & 31;
        const float a = tile[2*sp][d], b = tile[2*sp+1][d];
        const size_t p = ((size_t)bh * DK + d) * SEQ + s0 + 2 * sp;
        *(uint32_t*)(vth + p) = pack_h2(a, b);
    }
}

// ---------------------------------------------------------------------------
// Helper kernels
// ---------------------------------------------------------------------------
__global__ void fullmask_kernel(const int* __restrict__ amask, int* __restrict__ fm)
{
    const int b = blockIdx.y;
    const int q = blockIdx.x * blockDim.x + threadIdx.x;
    if (q >= SEQ) return;
    const int* m = amask + b * SEQ;
    int any = 0;
    for (int k = q + 1; k < SEQ; k++) { if (m[k]) { any = 1; break; } }
    fm[b * SEQ + q] = !any;
}

__global__ void __launch_bounds__(256) meanv_kernel(
    const float* __restrict__ V, float* __restrict__ mv)
{
    __shared__ float red[256];
    const int bh = blockIdx.x;
    const int tid = threadIdx.x;
    const int d = tid & 63, seg = tid >> 6;      // 4 segments of 512 rows
    const float* vb = V + (size_t)bh * SEQ * DK + d;
    float s = 0.f;
    for (int k = seg * 512; k < (seg + 1) * 512; k++) s += vb[(size_t)k * DK];
    red[tid] = s;
    __syncthreads();
    if (seg == 0)
        mv[bh * DK + d] = (red[d] + red[64 + d] + red[128 + d] + red[192 + d])
                          * (1.0f / SEQ);
}

// ---------------------------------------------------------------------------
// Flash attention via fp16 mma.sync: 128-row q-tiles (8 warps, 256 threads),
// triangular-paired (CTA qp handles q-tiles qp and 15-qp), cp.async
// double-buffered K/V (hi only), ldmatrix fragment loads.
// Scores: Qh*Kh + Ql*Kh.  PV: Ph*Vh + Pl*Vh (P split in-register).
// Mask: p = active ? exp(s-m) : 0; fully-masked rows overridden with meanV.
// ---------------------------------------------------------------------------
#define WS 36                        // uint32 words per 64-elem fp16 row (+pad)
#define TW (64*WS)                   // 2304 words per tile array
#define BUFW (2*TW)                  // 4608 words per buffer (KH, VH)
#define OMSKW (2*BUFW)               // mask area (2 x 64 ints)
#define ATT_SMEM ((OMSKW + 128)*4)   // 37376 bytes

__global__ void __launch_bounds__(256, 2) attn_mma_kernel(
    const __half* __restrict__ Qh, const __half* __restrict__ Ql,
    const __half* __restrict__ Kh, const __half* __restrict__ Vth,
    const int* __restrict__ amask, const int* __restrict__ fm,
    const float* __restrict__ meanV,
    __half* __restrict__ ctxH, __half* __restrict__ ctxL)
{
    extern __shared__ uint32_t sw[];
    const int tid = threadIdx.x;
    const int wid = tid >> 5, lane = tid & 31;
    const int g = lane >> 2, kq = lane & 3;
    const int alr = lane & 7, alh = (lane >> 3) & 1;
    const int qp = blockIdx.x, h = blockIdx.y, b = blockIdx.z;

    const size_t bhrow = (size_t)(b * NHEADS + h) * SEQ * DK;   // Q/K base
    const size_t bhcol = (size_t)(b * NHEADS + h) * DK * SEQ;   // VT base
    const int* amask_b = amask + b * SEQ;

    const uint32_t sbase = (uint32_t)__cvta_generic_to_shared(sw);

#pragma unroll 1
    for (int halfq = 0; halfq < 2; halfq++) {
        const int qt = (halfq == 0) ? qp : (15 - qp);   // 128-row q-tile id
        const int q0 = qt * 128;

        // ---- Q fragments straight from gmem (8 warps x 16 rows = 128) ----
        const int qr0 = q0 + wid * 16 + g;
        const int qr1 = qr0 + 8;
        uint32_t aQh[4][4], aQl[4][4];
        {
            const __half* r0h = Qh + bhrow + (size_t)qr0 * DK;
            const __half* r1h = Qh + bhrow + (size_t)qr1 * DK;
            const __half* r0l = Ql + bhrow + (size_t)qr0 * DK;
            const __half* r1l = Ql + bhrow + (size_t)qr1 * DK;
#pragma unroll
            for (int kc = 0; kc < 4; kc++) {
                const int kw = kc * 8 + kq;
                aQh[kc][0] = *(const uint32_t*)(r0h + kw * 2);
                aQh[kc][1] = *(const uint32_t*)(r1h + kw * 2);
                aQh[kc][2] = *(const uint32_t*)(r0h + (kw + 4) * 2);
                aQh[kc][3] = *(const uint32_t*)(r1h + (kw + 4) * 2);
                aQl[kc][0] = *(const uint32_t*)(r0l + kw * 2);
                aQl[kc][1] = *(const uint32_t*)(r1l + kw * 2);
                aQl[kc][2] = *(const uint32_t*)(r0l + (kw + 4) * 2);
                aQl[kc][3] = *(const uint32_t*)(r1l + (kw + 4) * 2);
            }
        }

        float m0 = -3.0e38f, m1 = -3.0e38f, l0 = 0.f, l1 = 0.f;
        float o[8][4];
#pragma unroll
        for (int dt = 0; dt < 8; dt++)
#pragma unroll
            for (int i = 0; i < 4; i++) o[dt][i] = 0.f;

        const int ktStart = qt * 2;        // first 64-key tile at the diagonal
        const int nkt = SEQ / 64 - ktStart;
        int buf = 0;

        // ---- prefetch first tile ----
        {
            const int k0 = ktStart * 64;
            const uint32_t bb = sbase + buf * (BUFW * 4);
            for (int idx = tid; idx < 512; idx += 256) {
                const int r = idx >> 3, ch = idx & 7;
                const uint32_t so = (r * WS + ch * 4) * 4;
                const size_t gk = bhrow + (size_t)(k0 + r) * DK + ch * 8;
                const size_t gv = bhcol + (size_t)r * SEQ + k0 + ch * 8;
                cpasync16(bb + so, Kh + gk);
                cpasync16(bb + TW * 4 + so, Vth + gv);
            }
            if (tid < 16)
                cpasync16(sbase + (OMSKW + buf * 64 + tid * 4) * 4,
                          amask_b + k0 + tid * 4);
        }
        CP_COMMIT();

#pragma unroll 1
        for (int i = 0; i < nkt; i++) {
            const int kt = ktStart + i;
            const int k0 = kt * 64;
            CP_WAIT0();
            __syncthreads();

            // ---- prefetch next tile into the other buffer ----
            if (i + 1 < nkt) {
                const int kn0 = k0 + 64;
                const uint32_t bb = sbase + (buf ^ 1) * (BUFW * 4);
                for (int idx = tid; idx < 512; idx += 256) {
                    const int r = idx >> 3, ch = idx & 7;
                    const uint32_t so = (r * WS + ch * 4) * 4;
                    const size_t gk = bhrow + (size_t)(kn0 + r) * DK + ch * 8;
                    const size_t gv = bhcol + (size_t)r * SEQ + kn0 + ch * 8;
                    cpasync16(bb + so, Kh + gk);
                    cpasync16(bb + TW * 4 + so, Vth + gv);
                }
                if (tid < 16)
                    cpasync16(sbase + (OMSKW + (buf ^ 1) * 64 + tid * 4) * 4,
                              amask_b + kn0 + tid * 4);
            }
            CP_COMMIT();

            const uint32_t kbb = sbase + (buf * BUFW) * 4;

            // ---- scores (ldmatrix K-hi fragments) ----
            float c[8][4];
#pragma unroll
            for (int nt = 0; nt < 8; nt++)
#pragma unroll
                for (int j = 0; j < 4; j++) c[nt][j] = 0.f;
#pragma unroll
            for (int kc = 0; kc < 4; kc++) {
#pragma unroll
                for (int nt = 0; nt < 8; nt++) {
                    const uint32_t aw = kbb +
                        ((nt * 8 + alr) * WS + kc * 8 + alh * 4) * 4;
                    uint32_t bh2[2];
                    ldsm_x2(bh2, aw);
                    mma16816(c[nt], aQh[kc], bh2);
                    mma16816(c[nt], aQl[kc], bh2);
                }
            }

            // ---- activity bits ----
            const int* mk = (const int*)(sw + OMSKW + buf * 64);
            uint32_t act0 = 0, act1 = 0;
#pragma unroll
            for (int nt = 0; nt < 8; nt++) {
#pragma unroll
                for (int e = 0; e < 2; e++) {
                    const int cl = nt * 8 + 2 * kq + e;
                    const int mv_ = mk[cl];
                    const int colg = k0 + cl;
                    if (mv_ && colg > qr0) act0 |= 1u << (nt * 2 + e);
                    if (mv_ && colg > qr1) act1 |= 1u << (nt * 2 + e);
                }
            }

            // ---- scale + masked tile max ----
            float t0 = -3.0e38f, t1 = -3.0e38f;
#pragma unroll
            for (int nt = 0; nt < 8; nt++) {
#pragma unroll
                for (int e = 0; e < 2; e++) {
                    float s0 = c[nt][e] * 0.125f;     c[nt][e] = s0;
                    float s1 = c[nt][2 + e] * 0.125f; c[nt][2 + e] = s1;
                    if ((act0 >> (nt * 2 + e)) & 1) t0 = fmaxf(t0, s0);
                    if ((act1 >> (nt * 2 + e)) & 1) t1 = fmaxf(t1, s1);
                }
            }
            t0 = fmaxf(t0, __shfl_xor_sync(0xffffffffu, t0, 1));
            t0 = fmaxf(t0, __shfl_xor_sync(0xffffffffu, t0, 2));
            t1 = fmaxf(t1, __shfl_xor_sync(0xffffffffu, t1, 1));
            t1 = fmaxf(t1, __shfl_xor_sync(0xffffffffu, t1, 2));

            const float mn0 = fmaxf(m0, t0), mn1 = fmaxf(m1, t1);
            const float cr0 = __expf(m0 - mn0), cr1 = __expf(m1 - mn1);
            m0 = mn0; m1 = mn1;

            // ---- p = exp or 0; row sums ----
            float rs0 = 0.f, rs1 = 0.f;
#pragma unroll
            for (int nt = 0; nt < 8; nt++) {
#pragma unroll
                for (int e = 0; e < 2; e++) {
                    float p0 = ((act0 >> (nt * 2 + e)) & 1)
                               ? __expf(c[nt][e] - mn0) : 0.f;
                    float p1 = ((act1 >> (nt * 2 + e)) & 1)
                               ? __expf(c[nt][2 + e] - mn1) : 0.f;
                    c[nt][e] = p0;     rs0 += p0;
                    c[nt][2 + e] = p1; rs1 += p1;
                }
            }
            rs0 += __shfl_xor_sync(0xffffffffu, rs0, 1);
            rs0 += __shfl_xor_sync(0xffffffffu, rs0, 2);
            rs1 += __shfl_xor_sync(0xffffffffu, rs1, 1);
            rs1 += __shfl_xor_sync(0xffffffffu, rs1, 2);
            l0 = l0 * cr0 + rs0;
            l1 = l1 * cr1 + rs1;

            // ---- rescale O, then O += P @ V (ldmatrix V-hi fragments) ----
#pragma unroll
            for (int dt = 0; dt < 8; dt++) {
                o[dt][0] *= cr0; o[dt][1] *= cr0;
                o[dt][2] *= cr1; o[dt][3] *= cr1;
            }
#pragma unroll
            for (int kc = 0; kc < 4; kc++) {
                const int tA = 2 * kc, tB = 2 * kc + 1;
                uint32_t aPh[4], aPl[4];
                {
                    __half h0 = __float2half_rn(c[tA][0]),
                           h1 = __float2half_rn(c[tA][1]);
                    __half h2 = __float2half_rn(c[tA][2]),
                           h3 = __float2half_rn(c[tA][3]);
                    __half h4 = __float2half_rn(c[tB][0]),
                           h5 = __float2half_rn(c[tB][1]);
                    __half h6 = __float2half_rn(c[tB][2]),
                           h7 = __float2half_rn(c[tB][3]);
                    aPh[0] = phbits(h0, h1); aPh[1] = phbits(h2, h3);
                    aPh[2] = phbits(h4, h5); aPh[3] = phbits(h6, h7);
                    aPl[0] = pack_h2(c[tA][0] - __half2float(h0),
                                     c[tA][1] - __half2float(h1));
                    aPl[1] = pack_h2(c[tA][2] - __half2float(h2),
                                     c[tA][3] - __half2float(h3));
                    aPl[2] = pack_h2(c[tB][0] - __half2float(h4),
                                     c[tB][1] - __half2float(h5));
                    aPl[3] = pack_h2(c[tB][2] - __half2float(h6),
                                     c[tB][3] - __half2float(h7));
                }
#pragma unroll
                for (int dt = 0; dt < 8; dt++) {
                    const uint32_t aw = kbb +
                        (TW + (dt * 8 + alr) * WS + kc * 8 + alh * 4) * 4;
                    uint32_t bh2[2];
                    ldsm_x2(bh2, aw);
                    mma16816(o[dt], aPh, bh2);
                    mma16816(o[dt], aPl, bh2);
                }
            }
            __syncthreads();
            buf ^= 1;
        }

        // ---- epilogue: write ctx as hi/lo fp16 ----
        const float inv0 = 1.0f / l0, inv1 = 1.0f / l1;
        const int fm0 = fm[b * SEQ + qr0];
        const int fm1 = fm[b * SEQ + qr1];
        const float* mvb = meanV + (size_t)(b * NHEADS + h) * DK;
#pragma unroll
        for (int dt = 0; dt < 8; dt++) {
            const int d = dt * 8 + 2 * kq;
            float2 mvv = *(const float2*)&mvb[d];
            float2 v0 = fm0 ? mvv : make_float2(o[dt][0] * inv0, o[dt][1] * inv0);
            float2 v1 = fm1 ? mvv : make_float2(o[dt][2] * inv1, o[dt][3] * inv1);
            const size_t p0 = (size_t)(b * SEQ + qr0) * DMODEL + h * DK + d;
            const size_t p1 = (size_t)(b * SEQ + qr1) * DMODEL + h * DK + d;
            __half a0 = __float2half_rn(v0.x), a1 = __float2half_rn(v0.y);
            __half b0 = __float2half_rn(v1.x), b1 = __float2half_rn(v1.y);
            *(uint32_t*)(ctxH + p0) = phbits(a0, a1);
            *(uint32_t*)(ctxL + p0) = pack_h2(v0.x - __half2float(a0),
                                              v0.y - __half2float(a1));
            *(uint32_t*)(ctxH + p1) = phbits(b0, b1);
            *(uint32_t*)(ctxL + p1) = pack_h2(v1.x - __half2float(b0),
                                              v1.y - __half2float(b1));
        }
    }
}

// ---------------------------------------------------------------------------
// LayerNorm: one CTA per token row (1024 elems, 256 threads)
// ---------------------------------------------------------------------------
__global__ void __launch_bounds__(256) ln_kernel(
    const float* __restrict__ x, const float* __restrict__ gamma,
    const float* __restrict__ beta, float* __restrict__ out)
{
    const int row = blockIdx.x;
    const int tid = threadIdx.x;
    const float* xr = x + (size_t)row * DMODEL;

    float4 v = *(const float4*)&xr[tid*4];
    float s  = v.x + v.y + v.z + v.w;
    float sq = v.x*v.x + v.y*v.y + v.z*v.z + v.w*v.w;
#pragma unroll
    for (int o = 16; o > 0; o >>= 1) {
        s  += __shfl_xor_sync(0xffffffffu, s,  o);
        sq += __shfl_xor_sync(0xffffffffu, sq, o);
    }
    __shared__ float ss[8], ssq[8], smu, sinv;
    const int wid = tid >> 5, lane = tid & 31;
    if (lane == 0) { ss[wid] = s; ssq[wid] = sq; }
    __syncthreads();
    if (tid == 0) {
        float S = 0.f, SQ = 0.f;
#pragma unroll
        for (int i = 0; i < 8; i++) { S += ss[i]; SQ += ssq[i]; }
        float mu = S * (1.0f/DMODEL);
        float var = SQ * (1.0f/DMODEL) - mu*mu;
        smu = mu;
        sinv = rsqrtf(var + 1e-5f);
    }
    __syncthreads();
    float mu = smu, inv = sinv;
    float4 g = *(const float4*)&gamma[tid*4];
    float4 be = *(const float4*)&beta[tid*4];
    float4 o;
    o.x = (v.x - mu) * inv * g.x + be.x;
    o.y = (v.y - mu) * inv * g.y + be.y;
    o.z = (v.z - mu) * inv * g.z + be.z;
    o.w = (v.w - mu) * inv * g.w + be.w;
    *(float4*)&out[(size_t)row*DMODEL + tid*4] = o;
}

// ---------------------------------------------------------------------------
extern "C" void kernel_launch(void* const* d_in, const int* in_sizes, int n_in,
                              void* d_out, int out_size)
{
    const float* inQ   = (const float*)d_in[0];
    const float* inK   = (const float*)d_in[1];
    const float* inV   = (const float*)d_in[2];
    const int*   amask = (const int*)  d_in[3];
    const float* W[4]  = { (const float*)d_in[4], (const float*)d_in[5],
                           (const float*)d_in[6], (const float*)d_in[7] };
    const float* gamma = (const float*)d_in[8];
    const float* beta  = (const float*)d_in[9];
    float* out = (float*)d_out;

    __half *inH, *inL, *WHp, *QH, *QL, *KH, *VTH, *ctxH, *ctxL;
    float *Vf, *tmp, *mv;
    int *fmp;
    cudaGetSymbolAddress((void**)&inH,  g_inH);
    cudaGetSymbolAddress((void**)&inL,  g_inL);
    cudaGetSymbolAddress((void**)&WHp,  g_WH);
    cudaGetSymbolAddress((void**)&QH,   g_QH);
    cudaGetSymbolAddress((void**)&QL,   g_QL);
    cudaGetSymbolAddress((void**)&KH,   g_KH);
    cudaGetSymbolAddress((void**)&Vf,   g_V);
    cudaGetSymbolAddress((void**)&VTH,  g_VTH);
    cudaGetSymbolAddress((void**)&ctxH, g_ctxH);
    cudaGetSymbolAddress((void**)&ctxL, g_ctxL);
    cudaGetSymbolAddress((void**)&tmp,  g_tmp);
    cudaGetSymbolAddress((void**)&mv,   g_meanV);
    cudaGetSymbolAddress((void**)&fmp,  g_fm);

    cudaFuncSetAttribute(attn_mma_kernel,
                         cudaFuncAttributeMaxDynamicSharedMemorySize, ATT_SMEM);
    cudaFuncSetAttribute(qkv_gemm_kernel,
                         cudaFuncAttributeMaxDynamicSharedMemorySize, G_SMEM);
    cudaFuncSetAttribute(outproj_gemm_kernel,
                         cudaFuncAttributeMaxDynamicSharedMemorySize, G_SMEM);

    // ---- one-time splits (inputs: hi+lo; weights: hi only) ----
    const float* ins[3] = { inQ, inK, inV };
    const int NIN = NTOK * DMODEL;         // 4M elements
    const int NW  = DMODEL * DMODEL;       // 1M elements
    SplitJobs sji{}, sjw{};
    for (int i = 0; i < 3; i++) {
        sji.x[i]  = (const float4*)ins[i];
        sji.hi[i] = (uint2*)(inH + (size_t)i * NIN);
        sji.lo[i] = (uint2*)(inL + (size_t)i * NIN);
    }
    sji.x[3] = sji.x[0]; sji.hi[3] = sji.hi[0]; sji.lo[3] = sji.lo[0];
    for (int i = 0; i < 4; i++) {
        sjw.x[i]  = (const float4*)W[i];
        sjw.hi[i] = (uint2*)(WHp + (size_t)i * NW);
        sjw.lo[i] = nullptr;
    }
    split_multi_kernel<<<dim3(NIN/4/256, 3), 256>>>(sji);
    split_hi_kernel<<<dim3(NW/4/256, 4), 256>>>(sjw);

    // ---- fused QKV projection (grid z selects Q/K/V) ----
    QKVPtrs qp;
    for (int i = 0; i < 3; i++) {
        qp.ah[i] = inH + (size_t)i * NIN;
        qp.al[i] = inL + (size_t)i * NIN;
        qp.wh[i] = WHp + (size_t)i * NW;
    }
    qkv_gemm_kernel<<<dim3(DMODEL/128, NTOK/128, 3), 256, G_SMEM>>>(
        qp, QH, QL, KH, Vf);

    vsplitT_kernel<<<dim3(SEQ/64, BH), 256>>>(Vf, VTH);
    fullmask_kernel<<<dim3(SEQ/1024, BATCH), 1024>>>(amask, fmp);
    meanv_kernel<<<BH, 256>>>(Vf, mv);

    attn_mma_kernel<<<dim3(8, NHEADS, BATCH), 256, ATT_SMEM>>>(
        QH, QL, KH, VTH, amask, fmp, mv, ctxH, ctxL);

    outproj_gemm_kernel<<<dim3(DMODEL/128, NTOK/128), 256, G_SMEM>>>(
        ctxH, ctxL, WHp + (size_t)3 * NW, inQ, tmp);

    ln_kernel<<<NTOK, 256>>>(tmp, gamma, beta, out);
}

// round 16
// speedup vs baseline: 1.5150x; 1.5150x over previous
#include <cuda_runtime.h>
#include <cuda_fp16.h>
#include <cstdint>

// Problem constants
#define BATCH 2
#define SEQ   2048
#define DMODEL 1024
#define NHEADS 16
#define DK    64
#define NTOK  (BATCH*SEQ)          // 4096
#define BH    (BATCH*NHEADS)       // 32

// ---------------------------------------------------------------------------
// Scratch (device globals; no runtime allocation allowed)
// fp16 2-term scheme: A-side operands keep (hi, lo); B-side operands keep hi
// only.  C = Ah*Bh + Al*Bh; dropped A*Bl term ~2^-12 relative (<< 1e-3).
// ---------------------------------------------------------------------------
__device__ __half g_inH[3][NTOK*DMODEL];    // split inputs (A-side: hi)
__device__ __half g_inL[3][NTOK*DMODEL];    //                      (lo)
__device__ __half g_WH[4][DMODEL*DMODEL];   // weights (B-side: hi only)
__device__ __half g_QH[BH*SEQ*DK], g_QL[BH*SEQ*DK];   // Q: A-side hi/lo
__device__ __half g_KH[BH*SEQ*DK];                    // K: B-side hi only
__device__ float  g_V [BH*SEQ*DK];                    // fp32 [b,h,s,d]
__device__ __half g_VTH[BH*DK*SEQ];                   // V^T: B-side hi only
__device__ __half g_ctxH[NTOK*DMODEL], g_ctxL[NTOK*DMODEL]; // ctx: A-side
__device__ float g_tmp[NTOK*DMODEL];         // pre-LN
__device__ float g_meanV[BH*DK];
__device__ int   g_fm[NTOK];                 // 1 if row has NO unmasked future key

// ---------------------------------------------------------------------------
// mma.sync m16n8k16 fp16 + ldmatrix (tcgen05 rejected by this ptxas target)
// ---------------------------------------------------------------------------
__device__ __forceinline__ void mma16816(float* c, const uint32_t* a,
                                         const uint32_t* b) {
    asm volatile(
        "mma.sync.aligned.m16n8k16.row.col.f32.f16.f16.f32 "
        "{%0,%1,%2,%3}, {%4,%5,%6,%7}, {%8,%9}, {%0,%1,%2,%3};"
        : "+f"(c[0]), "+f"(c[1]), "+f"(c[2]), "+f"(c[3])
        : "r"(a[0]), "r"(a[1]), "r"(a[2]), "r"(a[3]), "r"(b[0]), "r"(b[1]));
}
__device__ __forceinline__ void ldsm_x4(uint32_t* r, uint32_t addr) {
    asm volatile("ldmatrix.sync.aligned.m8n8.x4.shared.b16 {%0,%1,%2,%3}, [%4];"
                 : "=r"(r[0]), "=r"(r[1]), "=r"(r[2]), "=r"(r[3]) : "r"(addr));
}
__device__ __forceinline__ void ldsm_x2(uint32_t* r, uint32_t addr) {
    asm volatile("ldmatrix.sync.aligned.m8n8.x2.shared.b16 {%0,%1}, [%2];"
                 : "=r"(r[0]), "=r"(r[1]) : "r"(addr));
}

__device__ __forceinline__ uint32_t pack_h2(float a, float b) {
    __half2 t = __floats2half2_rn(a, b);
    return *(uint32_t*)&t;
}
__device__ __forceinline__ uint32_t phbits(__half a, __half b) {
    uint16_t ab = *(uint16_t*)&a, bb = *(uint16_t*)&b;
    return (uint32_t)ab | ((uint32_t)bb << 16);
}
__device__ __forceinline__ void cpasync16(uint32_t dst, const void* src) {
    asm volatile("cp.async.cg.shared.global [%0], [%1], 16;"
                 :: "r"(dst), "l"(src));
}
#define CP_COMMIT() asm volatile("cp.async.commit_group;" ::: "memory")
#define CP_WAIT0()  asm volatile("cp.async.wait_group 0;" ::: "memory")

// ---------------------------------------------------------------------------
// Split kernels: fp32 -> fp16 (hi, lo) for A-side; hi-only for B-side weights
// ---------------------------------------------------------------------------
struct SplitJobs {
    const float4* x[4];
    uint2* hi[4];
    uint2* lo[4];
};

__global__ void __launch_bounds__(256) split_multi_kernel(SplitJobs jb)
{
    const int t = blockIdx.y;
    const int i = blockIdx.x * 256 + threadIdx.x;
    float4 v = jb.x[t][i];
    __half h0 = __float2half_rn(v.x), h1 = __float2half_rn(v.y);
    __half h2 = __float2half_rn(v.z), h3 = __float2half_rn(v.w);
    jb.hi[t][i] = make_uint2(phbits(h0, h1), phbits(h2, h3));
    jb.lo[t][i] = make_uint2(
        pack_h2(v.x - __half2float(h0), v.y - __half2float(h1)),
        pack_h2(v.z - __half2float(h2), v.w - __half2float(h3)));
}

__global__ void __launch_bounds__(256) split_hi_kernel(SplitJobs jb)
{
    const int t = blockIdx.y;
    const int i = blockIdx.x * 256 + threadIdx.x;
    float4 v = jb.x[t][i];
    jb.hi[t][i] = make_uint2(
        pack_h2(v.x, v.y), pack_h2(v.z, v.w));
}

// ---------------------------------------------------------------------------
// GEMM body: C[m,n] = sum_k A[m,k]*W[n,k], A hi/lo fp16, W hi fp16.
// 2 terms: Ah*Wh + Al*Wh, fp32 accumulate.
// 128x128 CTA tile, 256 threads, k-chunk 32, cp.async double-buffered,
// ldmatrix fragment loads.
// ---------------------------------------------------------------------------
#define KC 32
#define SROW 20                // uint32 words per row (16 data words + 4 pad)
#define ARRW (128*SROW)        // 2560 words per array
#define GBUFW (3*ARRW)         // words per buffer (AH, AL, WH)
#define G_SMEM (2*GBUFW*4)     // 61440 bytes

__device__ __forceinline__ void gemm_body(
    const __half* __restrict__ Ah, const __half* __restrict__ Al,
    const __half* __restrict__ Wh,
    const float* __restrict__ resid, float* __restrict__ outF,
    __half* __restrict__ outH, __half* __restrict__ outL,
    int mode, uint32_t sb)
{
    const int tid  = threadIdx.x;
    const int wid  = tid >> 5;
    const int lane = tid & 31;
    const int bm = blockIdx.y * 128;
    const int bn = blockIdx.x * 128;

    const int mw = wid & 1;
    const int nw = wid >> 1;
    const int lr8 = lane & 7;
    const int lh  = (lane >> 3) & 1;
    const int lq  = lane >> 4;

    float acc[4][4][4];
#pragma unroll
    for (int mt = 0; mt < 4; mt++)
#pragma unroll
        for (int nt = 0; nt < 4; nt++)
#pragma unroll
            for (int i = 0; i < 4; i++) acc[mt][nt][i] = 0.f;

    auto prefetch = [&](int kt, int bsel) {
        const int kk = kt * KC;
        const uint32_t pb = sb + bsel * (GBUFW * 4);
#pragma unroll
        for (int it = 0; it < 2; it++) {
            const int idx = tid + it * 256;       // 0..511
            const int r  = idx >> 2;              // 0..127
            const int ch = idx & 3;               // 16B chunk
            const size_t ga = (size_t)(bm + r) * DMODEL + kk + ch * 8;
            const size_t gw = (size_t)(bn + r) * DMODEL + kk + ch * 8;
            const uint32_t so = (r * SROW + ch * 4) * 4;
            cpasync16(pb + so, Ah + ga);
            cpasync16(pb + ARRW * 4 + so, Al + ga);
            cpasync16(pb + 2 * ARRW * 4 + so, Wh + gw);
        }
    };

    int buf = 0;
    prefetch(0, 0);
    CP_COMMIT();

    for (int kt = 0; kt < DMODEL / KC; kt++) {
        CP_WAIT0();
        __syncthreads();
        if (kt + 1 < DMODEL / KC) prefetch(kt + 1, buf ^ 1);
        CP_COMMIT();

        const uint32_t bb = sb + buf * (GBUFW * 4);
#pragma unroll
        for (int ks = 0; ks < 2; ks++) {
            uint32_t bHf[4][2];
#pragma unroll
            for (int nt = 0; nt < 4; nt++) {
                const uint32_t aw = bb +
                    (2 * ARRW + (nw * 32 + nt * 8 + lr8) * SROW
                              + ks * 8 + lh * 4) * 4;
                ldsm_x2(bHf[nt], aw);
            }
#pragma unroll
            for (int mt = 0; mt < 4; mt++) {
                const uint32_t aw = bb +
                    ((mw * 64 + mt * 16 + lr8 + lh * 8) * SROW
                     + ks * 8 + lq * 4) * 4;
                uint32_t aH[4], aL[4];
                ldsm_x4(aH, aw);
                ldsm_x4(aL, aw + ARRW * 4);
#pragma unroll
                for (int nt = 0; nt < 4; nt++) {
                    mma16816(acc[mt][nt], aH, bHf[nt]);
                    mma16816(acc[mt][nt], aL, bHf[nt]);
                }
            }
        }
        __syncthreads();
        buf ^= 1;
    }

#pragma unroll
    for (int mt = 0; mt < 4; mt++) {
#pragma unroll
        for (int nt = 0; nt < 4; nt++) {
            const int m0 = bm + mw * 64 + mt * 16 + (lane >> 2);
            const int n  = bn + nw * 32 + nt * 8 + ((lane & 3) << 1);
#pragma unroll
            for (int half_ = 0; half_ < 2; half_++) {
                const int m = m0 + half_ * 8;
                const float c0 = acc[mt][nt][half_ * 2 + 0];
                const float c1 = acc[mt][nt][half_ * 2 + 1];
                if (mode == 1) {
                    const size_t off = (size_t)m * DMODEL + n;
                    float2 rs = *(const float2*)&resid[off];
                    *(float2*)&outF[off] = make_float2(c0 + rs.x, c1 + rs.y);
                } else {
                    const int b = m >> 11, s = m & 2047;
                    const int h = n >> 6, d0 = n & 63;
                    const size_t p =
                        ((size_t)(b * NHEADS + h) * SEQ + s) * DK + d0;
                    if (mode == 2) {
                        *(float2*)&outF[p] = make_float2(c0, c1);
                    } else {
                        __half h0 = __float2half_rn(c0);
                        __half h1 = __float2half_rn(c1);
                        *(uint32_t*)(outH + p) = phbits(h0, h1);
                        if (outL)
                            *(uint32_t*)(outL + p) =
                                pack_h2(c0 - __half2float(h0),
                                        c1 - __half2float(h1));
                    }
                }
            }
        }
    }
}

struct QKVPtrs {
    const __half *ah[3], *al[3], *wh[3];
};

__global__ void __launch_bounds__(256) qkv_gemm_kernel(
    QKVPtrs p, __half* qh, __half* ql, __half* kh, float* vout)
{
    extern __shared__ uint32_t gsm[];
    const uint32_t sb = (uint32_t)__cvta_generic_to_shared(gsm);
    const int z = blockIdx.z;
    __half* oh = (z == 0) ? qh : kh;
    __half* ol = (z == 0) ? ql : nullptr;   // K is B-side: hi only
    const int mode = (z == 2) ? 2 : 0;
    gemm_body(p.ah[z], p.al[z], p.wh[z], nullptr, vout, oh, ol, mode, sb);
}

__global__ void __launch_bounds__(256) outproj_gemm_kernel(
    const __half* __restrict__ ah, const __half* __restrict__ al,
    const __half* __restrict__ wh,
    const float* __restrict__ resid, float* __restrict__ outF)
{
    extern __shared__ uint32_t gsm[];
    const uint32_t sb = (uint32_t)__cvta_generic_to_shared(gsm);
    gemm_body(ah, al, wh, resid, outF, nullptr, nullptr, 1, sb);
}

// ---------------------------------------------------------------------------
// V transpose: [b,h,s,d] fp32 -> [b,h,d,s] fp16 hi (B-side of PV)
// ---------------------------------------------------------------------------
__global__ void __launch_bounds__(256) vsplitT_kernel(
    const float* __restrict__ V, __half* __restrict__ vth)
{
    __shared__ float tile[64][67];
    const int s0 = blockIdx.x * 64;
    const int bh = blockIdx.y;
    const float* vb = V + (size_t)bh * SEQ * DK;
    for (int idx = threadIdx.x; idx < 64 * 16; idx += 256) {
        const int r = idx >> 4, c4 = (idx & 15) << 2;
        float4 v = *(const float4*)&vb[(size_t)(s0 + r) * DK + c4];
        tile[r][c4] = v.x; tile[r][c4+1] = v.y;
        tile[r][c4+2] = v.z; tile[r][c4+3] = v.w;
    }
    __syncthreads();
    for (int idx = threadIdx.x; idx < 64 * 32; idx += 256) {
        const int d = idx >> 5, sp = idx & 31;
        const float a = tile[2*sp][d], b = tile[2*sp+1][d];
        const size_t p = ((size_t)bh * DK + d) * SEQ + s0 + 2 * sp;
        *(uint32_t*)(vth + p) = pack_h2(a, b);
    }
}

// ---------------------------------------------------------------------------
// Helper kernels
// ---------------------------------------------------------------------------
__global__ void fullmask_kernel(const int* __restrict__ amask, int* __restrict__ fm)
{
    const int b = blockIdx.y;
    const int q = blockIdx.x * blockDim.x + threadIdx.x;
    if (q >= SEQ) return;
    const int* m = amask + b * SEQ;
    int any = 0;
    for (int k = q + 1; k < SEQ; k++) { if (m[k]) { any = 1; break; } }
    fm[b * SEQ + q] = !any;
}

__global__ void __launch_bounds__(256) meanv_kernel(
    const float* __restrict__ V, float* __restrict__ mv)
{
    __shared__ float red[256];
    const int bh = blockIdx.x;
    const int tid = threadIdx.x;
    const int d = tid & 63, seg = tid >> 6;      // 4 segments of 512 rows
    const float* vb = V + (size_t)bh * SEQ * DK + d;
    float s = 0.f;
    for (int k = seg * 512; k < (seg + 1) * 512; k++) s += vb[(size_t)k * DK];
    red[tid] = s;
    __syncthreads();
    if (seg == 0)
        mv[bh * DK + d] = (red[d] + red[64 + d] + red[128 + d] + red[192 + d])
                          * (1.0f / SEQ);
}

// ---------------------------------------------------------------------------
// Flash attention via fp16 mma.sync: 128-row q-tiles (8 warps, 256 threads),
// triangular-paired (CTA qp handles q-tiles qp and 15-qp), cp.async
// double-buffered K/V (hi only), ldmatrix fragment loads.
// Scores: Qh*Kh + Ql*Kh.  PV: Ph*Vh + Pl*Vh (P split in-register).
// Mask: p = active ? exp(s-m) : 0; fully-masked rows overridden with meanV.
// ---------------------------------------------------------------------------
#define WS 36                        // uint32 words per 64-elem fp16 row (+pad)
#define TW (64*WS)                   // 2304 words per tile array
#define BUFW (2*TW)                  // 4608 words per buffer (KH, VH)
#define OMSKW (2*BUFW)               // mask area (2 x 64 ints)
#define ATT_SMEM ((OMSKW + 128)*4)   // 37376 bytes

__global__ void __launch_bounds__(256, 2) attn_mma_kernel(
    const __half* __restrict__ Qh, const __half* __restrict__ Ql,
    const __half* __restrict__ Kh, const __half* __restrict__ Vth,
    const int* __restrict__ amask, const int* __restrict__ fm,
    const float* __restrict__ meanV,
    __half* __restrict__ ctxH, __half* __restrict__ ctxL)
{
    extern __shared__ uint32_t sw[];
    const int tid = threadIdx.x;
    const int wid = tid >> 5, lane = tid & 31;
    const int g = lane >> 2, kq = lane & 3;
    const int alr = lane & 7, alh = (lane >> 3) & 1;
    const int qp = blockIdx.x, h = blockIdx.y, b = blockIdx.z;

    const size_t bhrow = (size_t)(b * NHEADS + h) * SEQ * DK;   // Q/K base
    const size_t bhcol = (size_t)(b * NHEADS + h) * DK * SEQ;   // VT base
    const int* amask_b = amask + b * SEQ;

    const uint32_t sbase = (uint32_t)__cvta_generic_to_shared(sw);

#pragma unroll 1
    for (int halfq = 0; halfq < 2; halfq++) {
        const int qt = (halfq == 0) ? qp : (15 - qp);   // 128-row q-tile id
        const int q0 = qt * 128;

        // ---- Q fragments straight from gmem (8 warps x 16 rows = 128) ----
        const int qr0 = q0 + wid * 16 + g;
        const int qr1 = qr0 + 8;
        uint32_t aQh[4][4], aQl[4][4];
        {
            const __half* r0h = Qh + bhrow + (size_t)qr0 * DK;
            const __half* r1h = Qh + bhrow + (size_t)qr1 * DK;
            const __half* r0l = Ql + bhrow + (size_t)qr0 * DK;
            const __half* r1l = Ql + bhrow + (size_t)qr1 * DK;
#pragma unroll
            for (int kc = 0; kc < 4; kc++) {
                const int kw = kc * 8 + kq;
                aQh[kc][0] = *(const uint32_t*)(r0h + kw * 2);
                aQh[kc][1] = *(const uint32_t*)(r1h + kw * 2);
                aQh[kc][2] = *(const uint32_t*)(r0h + (kw + 4) * 2);
                aQh[kc][3] = *(const uint32_t*)(r1h + (kw + 4) * 2);
                aQl[kc][0] = *(const uint32_t*)(r0l + kw * 2);
                aQl[kc][1] = *(const uint32_t*)(r1l + kw * 2);
                aQl[kc][2] = *(const uint32_t*)(r0l + (kw + 4) * 2);
                aQl[kc][3] = *(const uint32_t*)(r1l + (kw + 4) * 2);
            }
        }

        float m0 = -3.0e38f, m1 = -3.0e38f, l0 = 0.f, l1 = 0.f;
        float o[8][4];
#pragma unroll
        for (int dt = 0; dt < 8; dt++)
#pragma unroll
            for (int i = 0; i < 4; i++) o[dt][i] = 0.f;

        const int ktStart = qt * 2;        // first 64-key tile at the diagonal
        const int nkt = SEQ / 64 - ktStart;
        int buf = 0;

        // ---- prefetch first tile ----
        {
            const int k0 = ktStart * 64;
            const uint32_t bb = sbase + buf * (BUFW * 4);
            for (int idx = tid; idx < 512; idx += 256) {
                const int r = idx >> 3, ch = idx & 7;
                const uint32_t so = (r * WS + ch * 4) * 4;
                const size_t gk = bhrow + (size_t)(k0 + r) * DK + ch * 8;
                const size_t gv = bhcol + (size_t)r * SEQ + k0 + ch * 8;
                cpasync16(bb + so, Kh + gk);
                cpasync16(bb + TW * 4 + so, Vth + gv);
            }
            if (tid < 16)
                cpasync16(sbase + (OMSKW + buf * 64 + tid * 4) * 4,
                          amask_b + k0 + tid * 4);
        }
        CP_COMMIT();

#pragma unroll 1
        for (int i = 0; i < nkt; i++) {
            const int kt = ktStart + i;
            const int k0 = kt * 64;
            CP_WAIT0();
            __syncthreads();

            // ---- prefetch next tile into the other buffer ----
            if (i + 1 < nkt) {
                const int kn0 = k0 + 64;
                const uint32_t bb = sbase + (buf ^ 1) * (BUFW * 4);
                for (int idx = tid; idx < 512; idx += 256) {
                    const int r = idx >> 3, ch = idx & 7;
                    const uint32_t so = (r * WS + ch * 4) * 4;
                    const size_t gk = bhrow + (size_t)(kn0 + r) * DK + ch * 8;
                    const size_t gv = bhcol + (size_t)r * SEQ + kn0 + ch * 8;
                    cpasync16(bb + so, Kh + gk);
                    cpasync16(bb + TW * 4 + so, Vth + gv);
                }
                if (tid < 16)
                    cpasync16(sbase + (OMSKW + (buf ^ 1) * 64 + tid * 4) * 4,
                              amask_b + kn0 + tid * 4);
            }
            CP_COMMIT();

            const uint32_t kbb = sbase + (buf * BUFW) * 4;

            // ---- scores (ldmatrix K-hi fragments) ----
            float c[8][4];
#pragma unroll
            for (int nt = 0; nt < 8; nt++)
#pragma unroll
                for (int j = 0; j < 4; j++) c[nt][j] = 0.f;
#pragma unroll
            for (int kc = 0; kc < 4; kc++) {
#pragma unroll
                for (int nt = 0; nt < 8; nt++) {
                    const uint32_t aw = kbb +
                        ((nt * 8 + alr) * WS + kc * 8 + alh * 4) * 4;
                    uint32_t bh2[2];
                    ldsm_x2(bh2, aw);
                    mma16816(c[nt], aQh[kc], bh2);
                    mma16816(c[nt], aQl[kc], bh2);
                }
            }

            // ---- activity bits ----
            const int* mk = (const int*)(sw + OMSKW + buf * 64);
            uint32_t act0 = 0, act1 = 0;
#pragma unroll
            for (int nt = 0; nt < 8; nt++) {
#pragma unroll
                for (int e = 0; e < 2; e++) {
                    const int cl = nt * 8 + 2 * kq + e;
                    const int mv_ = mk[cl];
                    const int colg = k0 + cl;
                    if (mv_ && colg > qr0) act0 |= 1u << (nt * 2 + e);
                    if (mv_ && colg > qr1) act1 |= 1u << (nt * 2 + e);
                }
            }

            // ---- scale + masked tile max ----
            float t0 = -3.0e38f, t1 = -3.0e38f;
#pragma unroll
            for (int nt = 0; nt < 8; nt++) {
#pragma unroll
                for (int e = 0; e < 2; e++) {
                    float s0 = c[nt][e] * 0.125f;     c[nt][e] = s0;
                    float s1 = c[nt][2 + e] * 0.125f; c[nt][2 + e] = s1;
                    if ((act0 >> (nt * 2 + e)) & 1) t0 = fmaxf(t0, s0);
                    if ((act1 >> (nt * 2 + e)) & 1) t1 = fmaxf(t1, s1);
                }
            }
            t0 = fmaxf(t0, __shfl_xor_sync(0xffffffffu, t0, 1));
            t0 = fmaxf(t0, __shfl_xor_sync(0xffffffffu, t0, 2));
            t1 = fmaxf(t1, __shfl_xor_sync(0xffffffffu, t1, 1));
            t1 = fmaxf(t1, __shfl_xor_sync(0xffffffffu, t1, 2));

            const float mn0 = fmaxf(m0, t0), mn1 = fmaxf(m1, t1);
            const float cr0 = __expf(m0 - mn0), cr1 = __expf(m1 - mn1);
            m0 = mn0; m1 = mn1;

            // ---- p = exp or 0; row sums ----
            float rs0 = 0.f, rs1 = 0.f;
#pragma unroll
            for (int nt = 0; nt < 8; nt++) {
#pragma unroll
                for (int e = 0; e < 2; e++) {
                    float p0 = ((act0 >> (nt * 2 + e)) & 1)
                               ? __expf(c[nt][e] - mn0) : 0.f;
                    float p1 = ((act1 >> (nt * 2 + e)) & 1)
                               ? __expf(c[nt][2 + e] - mn1) : 0.f;
                    c[nt][e] = p0;     rs0 += p0;
                    c[nt][2 + e] = p1; rs1 += p1;
                }
            }
            rs0 += __shfl_xor_sync(0xffffffffu, rs0, 1);
            rs0 += __shfl_xor_sync(0xffffffffu, rs0, 2);
            rs1 += __shfl_xor_sync(0xffffffffu, rs1, 1);
            rs1 += __shfl_xor_sync(0xffffffffu, rs1, 2);
            l0 = l0 * cr0 + rs0;
            l1 = l1 * cr1 + rs1;

            // ---- rescale O, then O += P @ V (ldmatrix V-hi fragments) ----
#pragma unroll
            for (int dt = 0; dt < 8; dt++) {
                o[dt][0] *= cr0; o[dt][1] *= cr0;
                o[dt][2] *= cr1; o[dt][3] *= cr1;
            }
#pragma unroll
            for (int kc = 0; kc < 4; kc++) {
                const int tA = 2 * kc, tB = 2 * kc + 1;
                uint32_t aPh[4], aPl[4];
                {
                    __half h0 = __float2half_rn(c[tA][0]),
                           h1 = __float2half_rn(c[tA][1]);
                    __half h2 = __float2half_rn(c[tA][2]),
                           h3 = __float2half_rn(c[tA][3]);
                    __half h4 = __float2half_rn(c[tB][0]),
                           h5 = __float2half_rn(c[tB][1]);
                    __half h6 = __float2half_rn(c[tB][2]),
                           h7 = __float2half_rn(c[tB][3]);
                    aPh[0] = phbits(h0, h1); aPh[1] = phbits(h2, h3);
                    aPh[2] = phbits(h4, h5); aPh[3] = phbits(h6, h7);
                    aPl[0] = pack_h2(c[tA][0] - __half2float(h0),
                                     c[tA][1] - __half2float(h1));
                    aPl[1] = pack_h2(c[tA][2] - __half2float(h2),
                                     c[tA][3] - __half2float(h3));
                    aPl[2] = pack_h2(c[tB][0] - __half2float(h4),
                                     c[tB][1] - __half2float(h5));
                    aPl[3] = pack_h2(c[tB][2] - __half2float(h6),
                                     c[tB][3] - __half2float(h7));
                }
#pragma unroll
                for (int dt = 0; dt < 8; dt++) {
                    const uint32_t aw = kbb +
                        (TW + (dt * 8 + alr) * WS + kc * 8 + alh * 4) * 4;
                    uint32_t bh2[2];
                    ldsm_x2(bh2, aw);
                    mma16816(o[dt], aPh, bh2);
                    mma16816(o[dt], aPl, bh2);
                }
            }
            __syncthreads();
            buf ^= 1;
        }

        // ---- epilogue: write ctx as hi/lo fp16 ----
        const float inv0 = 1.0f / l0, inv1 = 1.0f / l1;
        const int fm0 = fm[b * SEQ + qr0];
        const int fm1 = fm[b * SEQ + qr1];
        const float* mvb = meanV + (size_t)(b * NHEADS + h) * DK;
#pragma unroll
        for (int dt = 0; dt < 8; dt++) {
            const int d = dt * 8 + 2 * kq;
            float2 mvv = *(const float2*)&mvb[d];
            float2 v0 = fm0 ? mvv : make_float2(o[dt][0] * inv0, o[dt][1] * inv0);
            float2 v1 = fm1 ? mvv : make_float2(o[dt][2] * inv1, o[dt][3] * inv1);
            const size_t p0 = (size_t)(b * SEQ + qr0) * DMODEL + h * DK + d;
            const size_t p1 = (size_t)(b * SEQ + qr1) * DMODEL + h * DK + d;
            __half a0 = __float2half_rn(v0.x), a1 = __float2half_rn(v0.y);
            __half b0 = __float2half_rn(v1.x), b1 = __float2half_rn(v1.y);
            *(uint32_t*)(ctxH + p0) = phbits(a0, a1);
            *(uint32_t*)(ctxL + p0) = pack_h2(v0.x - __half2float(a0),
                                              v0.y - __half2float(a1));
            *(uint32_t*)(ctxH + p1) = phbits(b0, b1);
            *(uint32_t*)(ctxL + p1) = pack_h2(v1.x - __half2float(b0),
                                              v1.y - __half2float(b1));
        }
    }
}

// ---------------------------------------------------------------------------
// LayerNorm: one CTA per token row (1024 elems, 256 threads)
// ---------------------------------------------------------------------------
__global__ void __launch_bounds__(256) ln_kernel(
    const float* __restrict__ x, const float* __restrict__ gamma,
    const float* __restrict__ beta, float* __restrict__ out)
{
    const int row = blockIdx.x;
    const int tid = threadIdx.x;
    const float* xr = x + (size_t)row * DMODEL;

    float4 v = *(const float4*)&xr[tid*4];
    float s  = v.x + v.y + v.z + v.w;
    float sq = v.x*v.x + v.y*v.y + v.z*v.z + v.w*v.w;
#pragma unroll
    for (int o = 16; o > 0; o >>= 1) {
        s  += __shfl_xor_sync(0xffffffffu, s,  o);
        sq += __shfl_xor_sync(0xffffffffu, sq, o);
    }
    __shared__ float ss[8], ssq[8], smu, sinv;
    const int wid = tid >> 5, lane = tid & 31;
    if (lane == 0) { ss[wid] = s; ssq[wid] = sq; }
    __syncthreads();
    if (tid == 0) {
        float S = 0.f, SQ = 0.f;
#pragma unroll
        for (int i = 0; i < 8; i++) { S += ss[i]; SQ += ssq[i]; }
        float mu = S * (1.0f/DMODEL);
        float var = SQ * (1.0f/DMODEL) - mu*mu;
        smu = mu;
        sinv = rsqrtf(var + 1e-5f);
    }
    __syncthreads();
    float mu = smu, inv = sinv;
    float4 g = *(const float4*)&gamma[tid*4];
    float4 be = *(const float4*)&beta[tid*4];
    float4 o;
    o.x = (v.x - mu) * inv * g.x + be.x;
    o.y = (v.y - mu) * inv * g.y + be.y;
    o.z = (v.z - mu) * inv * g.z + be.z;
    o.w = (v.w - mu) * inv * g.w + be.w;
    *(float4*)&out[(size_t)row*DMODEL + tid*4] = o;
}

// ---------------------------------------------------------------------------
extern "C" void kernel_launch(void* const* d_in, const int* in_sizes, int n_in,
                              void* d_out, int out_size)
{
    const float* inQ   = (const float*)d_in[0];
    const float* inK   = (const float*)d_in[1];
    const float* inV   = (const float*)d_in[2];
    const int*   amask = (const int*)  d_in[3];
    const float* W[4]  = { (const float*)d_in[4], (const float*)d_in[5],
                           (const float*)d_in[6], (const float*)d_in[7] };
    const float* gamma = (const float*)d_in[8];
    const float* beta  = (const float*)d_in[9];
    float* out = (float*)d_out;

    __half *inH, *inL, *WHp, *QH, *QL, *KH, *VTH, *ctxH, *ctxL;
    float *Vf, *tmp, *mv;
    int *fmp;
    cudaGetSymbolAddress((void**)&inH,  g_inH);
    cudaGetSymbolAddress((void**)&inL,  g_inL);
    cudaGetSymbolAddress((void**)&WHp,  g_WH);
    cudaGetSymbolAddress((void**)&QH,   g_QH);
    cudaGetSymbolAddress((void**)&QL,   g_QL);
    cudaGetSymbolAddress((void**)&KH,   g_KH);
    cudaGetSymbolAddress((void**)&Vf,   g_V);
    cudaGetSymbolAddress((void**)&VTH,  g_VTH);
    cudaGetSymbolAddress((void**)&ctxH, g_ctxH);
    cudaGetSymbolAddress((void**)&ctxL, g_ctxL);
    cudaGetSymbolAddress((void**)&tmp,  g_tmp);
    cudaGetSymbolAddress((void**)&mv,   g_meanV);
    cudaGetSymbolAddress((void**)&fmp,  g_fm);

    cudaFuncSetAttribute(attn_mma_kernel,
                         cudaFuncAttributeMaxDynamicSharedMemorySize, ATT_SMEM);
    cudaFuncSetAttribute(qkv_gemm_kernel,
                         cudaFuncAttributeMaxDynamicSharedMemorySize, G_SMEM);
    cudaFuncSetAttribute(outproj_gemm_kernel,
                         cudaFuncAttributeMaxDynamicSharedMemorySize, G_SMEM);

    // ---- one-time splits (inputs: hi+lo; weights: hi only) ----
    const float* ins[3] = { inQ, inK, inV };
    const int NIN = NTOK * DMODEL;         // 4M elements
    const int NW  = DMODEL * DMODEL;       // 1M elements
    SplitJobs sji{}, sjw{};
    for (int i = 0; i < 3; i++) {
        sji.x[i]  = (const float4*)ins[i];
        sji.hi[i] = (uint2*)(inH + (size_t)i * NIN);
        sji.lo[i] = (uint2*)(inL + (size_t)i * NIN);
    }
    sji.x[3] = sji.x[0]; sji.hi[3] = sji.hi[0]; sji.lo[3] = sji.lo[0];
    for (int i = 0; i < 4; i++) {
        sjw.x[i]  = (const float4*)W[i];
        sjw.hi[i] = (uint2*)(WHp + (size_t)i * NW);
        sjw.lo[i] = nullptr;
    }
    split_multi_kernel<<<dim3(NIN/4/256, 3), 256>>>(sji);
    split_hi_kernel<<<dim3(NW/4/256, 4), 256>>>(sjw);

    // ---- fused QKV projection (grid z selects Q/K/V) ----
    QKVPtrs qp;
    for (int i = 0; i < 3; i++) {
        qp.ah[i] = inH + (size_t)i * NIN;
        qp.al[i] = inL + (size_t)i * NIN;
        qp.wh[i] = WHp + (size_t)i * NW;
    }
    qkv_gemm_kernel<<<dim3(DMODEL/128, NTOK/128, 3), 256, G_SMEM>>>(
        qp, QH, QL, KH, Vf);

    vsplitT_kernel<<<dim3(SEQ/64, BH), 256>>>(Vf, VTH);
    fullmask_kernel<<<dim3(SEQ/1024, BATCH), 1024>>>(amask, fmp);
    meanv_kernel<<<BH, 256>>>(Vf, mv);

    attn_mma_kernel<<<dim3(8, NHEADS, BATCH), 256, ATT_SMEM>>>(
        QH, QL, KH, VTH, amask, fmp, mv, ctxH, ctxL);

    outproj_gemm_kernel<<<dim3(DMODEL/128, NTOK/128), 256, G_SMEM>>>(
        ctxH, ctxL, WHp + (size_t)3 * NW, inQ, tmp);

    ln_kernel<<<NTOK, 256>>>(tmp, gamma, beta, out);
}

// round 17
// speedup vs baseline: 2.2351x; 1.4753x over previous
#include <cuda_runtime.h>
#include <cuda_fp16.h>
#include <cstdint>

// Problem constants
#define BATCH 2
#define SEQ   2048
#define DMODEL 1024
#define NHEADS 16
#define DK    64
#define NTOK  (BATCH*SEQ)          // 4096
#define BH    (BATCH*NHEADS)       // 32

// ---------------------------------------------------------------------------
// Scratch (device globals; no runtime allocation allowed)
// Pure fp16 single-term scheme: all MMA operands rounded to fp16.
// Calibrated error model: final rel_err ~ 4.5e-7 * 2^(16-11) * sqrt(2) ~ 2e-5.
// ---------------------------------------------------------------------------
__device__ __half g_inH[3][NTOK*DMODEL];    // fp16 inputs (Q,K,V)
__device__ __half g_WH[4][DMODEL*DMODEL];   // fp16 weights
__device__ __half g_QH[BH*SEQ*DK];          // Q [b,h,s,d]
__device__ __half g_KH[BH*SEQ*DK];          // K [b,h,s,d]
__device__ float  g_V [BH*SEQ*DK];          // fp32 [b,h,s,d]
__device__ __half g_VTH[BH*DK*SEQ];         // V^T [b,h,d,s]
__device__ __half g_ctxH[NTOK*DMODEL];      // attention output
__device__ float g_tmp[NTOK*DMODEL];        // pre-LN
__device__ float g_meanV[BH*DK];
__device__ int   g_fm[NTOK];                // 1 if row has NO unmasked future key

// ---------------------------------------------------------------------------
// mma.sync m16n8k16 fp16 + ldmatrix (tcgen05 rejected by this ptxas target)
// ---------------------------------------------------------------------------
__device__ __forceinline__ void mma16816(float* c, const uint32_t* a,
                                         const uint32_t* b) {
    asm volatile(
        "mma.sync.aligned.m16n8k16.row.col.f32.f16.f16.f32 "
        "{%0,%1,%2,%3}, {%4,%5,%6,%7}, {%8,%9}, {%0,%1,%2,%3};"
        : "+f"(c[0]), "+f"(c[1]), "+f"(c[2]), "+f"(c[3])
        : "r"(a[0]), "r"(a[1]), "r"(a[2]), "r"(a[3]), "r"(b[0]), "r"(b[1]));
}
__device__ __forceinline__ void ldsm_x4(uint32_t* r, uint32_t addr) {
    asm volatile("ldmatrix.sync.aligned.m8n8.x4.shared.b16 {%0,%1,%2,%3}, [%4];"
                 : "=r"(r[0]), "=r"(r[1]), "=r"(r[2]), "=r"(r[3]) : "r"(addr));
}
__device__ __forceinline__ void ldsm_x2(uint32_t* r, uint32_t addr) {
    asm volatile("ldmatrix.sync.aligned.m8n8.x2.shared.b16 {%0,%1}, [%2];"
                 : "=r"(r[0]), "=r"(r[1]) : "r"(addr));
}

__device__ __forceinline__ uint32_t pack_h2(float a, float b) {
    __half2 t = __floats2half2_rn(a, b);
    return *(uint32_t*)&t;
}
__device__ __forceinline__ uint32_t phbits(__half a, __half b) {
    uint16_t ab = *(uint16_t*)&a, bb = *(uint16_t*)&b;
    return (uint32_t)ab | ((uint32_t)bb << 16);
}
__device__ __forceinline__ void cpasync16(uint32_t dst, const void* src) {
    asm volatile("cp.async.cg.shared.global [%0], [%1], 16;"
                 :: "r"(dst), "l"(src));
}
#define CP_COMMIT() asm volatile("cp.async.commit_group;" ::: "memory")
#define CP_WAIT0()  asm volatile("cp.async.wait_group 0;" ::: "memory")

// ---------------------------------------------------------------------------
// Split kernel: fp32 -> fp16, multi-tensor via grid.y
// ---------------------------------------------------------------------------
struct SplitJobs {
    const float4* x[4];
    uint2* hi[4];
};

__global__ void __launch_bounds__(256) split_hi_kernel(SplitJobs jb)
{
    const int t = blockIdx.y;
    const int i = blockIdx.x * 256 + threadIdx.x;
    float4 v = jb.x[t][i];
    jb.hi[t][i] = make_uint2(pack_h2(v.x, v.y), pack_h2(v.z, v.w));
}

// ---------------------------------------------------------------------------
// GEMM body: C[m,n] = sum_k A[m,k]*W[n,k], pure fp16 operands, fp32 accum.
// 128x128 CTA tile, 256 threads, k-chunk 32, cp.async double-buffered,
// ldmatrix fragment loads.
// ---------------------------------------------------------------------------
#define KC 32
#define SROW 20                // uint32 words per row (16 data words + 4 pad)
#define ARRW (128*SROW)        // 2560 words per array
#define GBUFW (2*ARRW)         // words per buffer (A, W)
#define G_SMEM (2*GBUFW*4)     // 40960 bytes

__device__ __forceinline__ void gemm_body(
    const __half* __restrict__ Ah, const __half* __restrict__ Wh,
    const float* __restrict__ resid, float* __restrict__ outF,
    __half* __restrict__ outH, int mode, uint32_t sb)
{
    const int tid  = threadIdx.x;
    const int wid  = tid >> 5;
    const int lane = tid & 31;
    const int bm = blockIdx.y * 128;
    const int bn = blockIdx.x * 128;

    const int mw = wid & 1;
    const int nw = wid >> 1;
    const int lr8 = lane & 7;
    const int lh  = (lane >> 3) & 1;
    const int lq  = lane >> 4;

    float acc[4][4][4];
#pragma unroll
    for (int mt = 0; mt < 4; mt++)
#pragma unroll
        for (int nt = 0; nt < 4; nt++)
#pragma unroll
            for (int i = 0; i < 4; i++) acc[mt][nt][i] = 0.f;

    auto prefetch = [&](int kt, int bsel) {
        const int kk = kt * KC;
        const uint32_t pb = sb + bsel * (GBUFW * 4);
#pragma unroll
        for (int it = 0; it < 2; it++) {
            const int idx = tid + it * 256;       // 0..511
            const int r  = idx >> 2;              // 0..127
            const int ch = idx & 3;               // 16B chunk
            const size_t ga = (size_t)(bm + r) * DMODEL + kk + ch * 8;
            const size_t gw = (size_t)(bn + r) * DMODEL + kk + ch * 8;
            const uint32_t so = (r * SROW + ch * 4) * 4;
            cpasync16(pb + so, Ah + ga);
            cpasync16(pb + ARRW * 4 + so, Wh + gw);
        }
    };

    int buf = 0;
    prefetch(0, 0);
    CP_COMMIT();

    for (int kt = 0; kt < DMODEL / KC; kt++) {
        CP_WAIT0();
        __syncthreads();
        if (kt + 1 < DMODEL / KC) prefetch(kt + 1, buf ^ 1);
        CP_COMMIT();

        const uint32_t bb = sb + buf * (GBUFW * 4);
#pragma unroll
        for (int ks = 0; ks < 2; ks++) {
            uint32_t bHf[4][2];
#pragma unroll
            for (int nt = 0; nt < 4; nt++) {
                const uint32_t aw = bb +
                    (ARRW + (nw * 32 + nt * 8 + lr8) * SROW
                          + ks * 8 + lh * 4) * 4;
                ldsm_x2(bHf[nt], aw);
            }
#pragma unroll
            for (int mt = 0; mt < 4; mt++) {
                const uint32_t aw = bb +
                    ((mw * 64 + mt * 16 + lr8 + lh * 8) * SROW
                     + ks * 8 + lq * 4) * 4;
                uint32_t aH[4];
                ldsm_x4(aH, aw);
#pragma unroll
                for (int nt = 0; nt < 4; nt++)
                    mma16816(acc[mt][nt], aH, bHf[nt]);
            }
        }
        __syncthreads();
        buf ^= 1;
    }

#pragma unroll
    for (int mt = 0; mt < 4; mt++) {
#pragma unroll
        for (int nt = 0; nt < 4; nt++) {
            const int m0 = bm + mw * 64 + mt * 16 + (lane >> 2);
            const int n  = bn + nw * 32 + nt * 8 + ((lane & 3) << 1);
#pragma unroll
            for (int half_ = 0; half_ < 2; half_++) {
                const int m = m0 + half_ * 8;
                const float c0 = acc[mt][nt][half_ * 2 + 0];
                const float c1 = acc[mt][nt][half_ * 2 + 1];
                if (mode == 1) {
                    const size_t off = (size_t)m * DMODEL + n;
                    float2 rs = *(const float2*)&resid[off];
                    *(float2*)&outF[off] = make_float2(c0 + rs.x, c1 + rs.y);
                } else {
                    const int b = m >> 11, s = m & 2047;
                    const int h = n >> 6, d0 = n & 63;
                    const size_t p =
                        ((size_t)(b * NHEADS + h) * SEQ + s) * DK + d0;
                    if (mode == 2) {
                        *(float2*)&outF[p] = make_float2(c0, c1);
                    } else {
                        *(uint32_t*)(outH + p) = pack_h2(c0, c1);
                    }
                }
            }
        }
    }
}

struct QKVPtrs {
    const __half *ah[3], *wh[3];
};

__global__ void __launch_bounds__(256) qkv_gemm_kernel(
    QKVPtrs p, __half* qh, __half* kh, float* vout)
{
    extern __shared__ uint32_t gsm[];
    const uint32_t sb = (uint32_t)__cvta_generic_to_shared(gsm);
    const int z = blockIdx.z;
    __half* oh = (z == 0) ? qh : kh;
    const int mode = (z == 2) ? 2 : 0;
    gemm_body(p.ah[z], p.wh[z], nullptr, vout, oh, mode, sb);
}

__global__ void __launch_bounds__(256) outproj_gemm_kernel(
    const __half* __restrict__ ah, const __half* __restrict__ wh,
    const float* __restrict__ resid, float* __restrict__ outF)
{
    extern __shared__ uint32_t gsm[];
    const uint32_t sb = (uint32_t)__cvta_generic_to_shared(gsm);
    gemm_body(ah, wh, resid, outF, nullptr, 1, sb);
}

// ---------------------------------------------------------------------------
// V transpose: [b,h,s,d] fp32 -> [b,h,d,s] fp16
// ---------------------------------------------------------------------------
__global__ void __launch_bounds__(256) vsplitT_kernel(
    const float* __restrict__ V, __half* __restrict__ vth)
{
    __shared__ float tile[64][67];
    const int s0 = blockIdx.x * 64;
    const int bh = blockIdx.y;
    const float* vb = V + (size_t)bh * SEQ * DK;
    for (int idx = threadIdx.x; idx < 64 * 16; idx += 256) {
        const int r = idx >> 4, c4 = (idx & 15) << 2;
        float4 v = *(const float4*)&vb[(size_t)(s0 + r) * DK + c4];
        tile[r][c4] = v.x; tile[r][c4+1] = v.y;
        tile[r][c4+2] = v.z; tile[r][c4+3] = v.w;
    }
    __syncthreads();
    for (int idx = threadIdx.x; idx < 64 * 32; idx += 256) {
        const int d = idx >> 5, sp = idx & 31;
        const float a = tile[2*sp][d], b = tile[2*sp+1][d];
        const size_t p = ((size_t)bh * DK + d) * SEQ + s0 + 2 * sp;
        *(uint32_t*)(vth + p) = pack_h2(a, b);
    }
}

// ---------------------------------------------------------------------------
// Helper kernels
// ---------------------------------------------------------------------------
__global__ void fullmask_kernel(const int* __restrict__ amask, int* __restrict__ fm)
{
    const int b = blockIdx.y;
    const int q = blockIdx.x * blockDim.x + threadIdx.x;
    if (q >= SEQ) return;
    const int* m = amask + b * SEQ;
    int any = 0;
    for (int k = q + 1; k < SEQ; k++) { if (m[k]) { any = 1; break; } }
    fm[b * SEQ + q] = !any;
}

__global__ void __launch_bounds__(256) meanv_kernel(
    const float* __restrict__ V, float* __restrict__ mv)
{
    __shared__ float red[256];
    const int bh = blockIdx.x;
    const int tid = threadIdx.x;
    const int d = tid & 63, seg = tid >> 6;      // 4 segments of 512 rows
    const float* vb = V + (size_t)bh * SEQ * DK + d;
    float s = 0.f;
    for (int k = seg * 512; k < (seg + 1) * 512; k++) s += vb[(size_t)k * DK];
    red[tid] = s;
    __syncthreads();
    if (seg == 0)
        mv[bh * DK + d] = (red[d] + red[64 + d] + red[128 + d] + red[192 + d])
                          * (1.0f / SEQ);
}

// ---------------------------------------------------------------------------
// Flash attention via fp16 mma.sync (single-term): 128-row q-tiles (8 warps,
// 256 threads), triangular-paired (CTA qp handles q-tiles qp and 15-qp),
// cp.async double-buffered K/V, ldmatrix fragment loads.
// Mask: p = active ? exp(s-m) : 0; fully-masked rows overridden with meanV.
// ---------------------------------------------------------------------------
#define WS 36                        // uint32 words per 64-elem fp16 row (+pad)
#define TW (64*WS)                   // 2304 words per tile array
#define BUFW (2*TW)                  // 4608 words per buffer (K, V)
#define OMSKW (2*BUFW)               // mask area (2 x 64 ints)
#define ATT_SMEM ((OMSKW + 128)*4)   // 37376 bytes

__global__ void __launch_bounds__(256, 2) attn_mma_kernel(
    const __half* __restrict__ Qh, const __half* __restrict__ Kh,
    const __half* __restrict__ Vth,
    const int* __restrict__ amask, const int* __restrict__ fm,
    const float* __restrict__ meanV, __half* __restrict__ ctxH)
{
    extern __shared__ uint32_t sw[];
    const int tid = threadIdx.x;
    const int wid = tid >> 5, lane = tid & 31;
    const int g = lane >> 2, kq = lane & 3;
    const int alr = lane & 7, alh = (lane >> 3) & 1;
    const int qp = blockIdx.x, h = blockIdx.y, b = blockIdx.z;

    const size_t bhrow = (size_t)(b * NHEADS + h) * SEQ * DK;   // Q/K base
    const size_t bhcol = (size_t)(b * NHEADS + h) * DK * SEQ;   // VT base
    const int* amask_b = amask + b * SEQ;

    const uint32_t sbase = (uint32_t)__cvta_generic_to_shared(sw);

#pragma unroll 1
    for (int halfq = 0; halfq < 2; halfq++) {
        const int qt = (halfq == 0) ? qp : (15 - qp);   // 128-row q-tile id
        const int q0 = qt * 128;

        // ---- Q fragments straight from gmem (8 warps x 16 rows = 128) ----
        const int qr0 = q0 + wid * 16 + g;
        const int qr1 = qr0 + 8;
        uint32_t aQh[4][4];
        {
            const __half* r0h = Qh + bhrow + (size_t)qr0 * DK;
            const __half* r1h = Qh + bhrow + (size_t)qr1 * DK;
#pragma unroll
            for (int kc = 0; kc < 4; kc++) {
                const int kw = kc * 8 + kq;
                aQh[kc][0] = *(const uint32_t*)(r0h + kw * 2);
                aQh[kc][1] = *(const uint32_t*)(r1h + kw * 2);
                aQh[kc][2] = *(const uint32_t*)(r0h + (kw + 4) * 2);
                aQh[kc][3] = *(const uint32_t*)(r1h + (kw + 4) * 2);
            }
        }

        float m0 = -3.0e38f, m1 = -3.0e38f, l0 = 0.f, l1 = 0.f;
        float o[8][4];
#pragma unroll
        for (int dt = 0; dt < 8; dt++)
#pragma unroll
            for (int i = 0; i < 4; i++) o[dt][i] = 0.f;

        const int ktStart = qt * 2;        // first 64-key tile at the diagonal
        const int nkt = SEQ / 64 - ktStart;
        int buf = 0;

        // ---- prefetch first tile ----
        {
            const int k0 = ktStart * 64;
            const uint32_t bb = sbase + buf * (BUFW * 4);
            for (int idx = tid; idx < 512; idx += 256) {
                const int r = idx >> 3, ch = idx & 7;
                const uint32_t so = (r * WS + ch * 4) * 4;
                const size_t gk = bhrow + (size_t)(k0 + r) * DK + ch * 8;
                const size_t gv = bhcol + (size_t)r * SEQ + k0 + ch * 8;
                cpasync16(bb + so, Kh + gk);
                cpasync16(bb + TW * 4 + so, Vth + gv);
            }
            if (tid < 16)
                cpasync16(sbase + (OMSKW + buf * 64 + tid * 4) * 4,
                          amask_b + k0 + tid * 4);
        }
        CP_COMMIT();

#pragma unroll 1
        for (int i = 0; i < nkt; i++) {
            const int kt = ktStart + i;
            const int k0 = kt * 64;
            CP_WAIT0();
            __syncthreads();

            // ---- prefetch next tile into the other buffer ----
            if (i + 1 < nkt) {
                const int kn0 = k0 + 64;
                const uint32_t bb = sbase + (buf ^ 1) * (BUFW * 4);
                for (int idx = tid; idx < 512; idx += 256) {
                    const int r = idx >> 3, ch = idx & 7;
                    const uint32_t so = (r * WS + ch * 4) * 4;
                    const size_t gk = bhrow + (size_t)(kn0 + r) * DK + ch * 8;
                    const size_t gv = bhcol + (size_t)r * SEQ + kn0 + ch * 8;
                    cpasync16(bb + so, Kh + gk);
                    cpasync16(bb + TW * 4 + so, Vth + gv);
                }
                if (tid < 16)
                    cpasync16(sbase + (OMSKW + (buf ^ 1) * 64 + tid * 4) * 4,
                              amask_b + kn0 + tid * 4);
            }
            CP_COMMIT();

            const uint32_t kbb = sbase + (buf * BUFW) * 4;

            // ---- scores (ldmatrix K fragments) ----
            float c[8][4];
#pragma unroll
            for (int nt = 0; nt < 8; nt++)
#pragma unroll
                for (int j = 0; j < 4; j++) c[nt][j] = 0.f;
#pragma unroll
            for (int kc = 0; kc < 4; kc++) {
#pragma unroll
                for (int nt = 0; nt < 8; nt++) {
                    const uint32_t aw = kbb +
                        ((nt * 8 + alr) * WS + kc * 8 + alh * 4) * 4;
                    uint32_t bh2[2];
                    ldsm_x2(bh2, aw);
                    mma16816(c[nt], aQh[kc], bh2);
                }
            }

            // ---- activity bits ----
            const int* mk = (const int*)(sw + OMSKW + buf * 64);
            uint32_t act0 = 0, act1 = 0;
#pragma unroll
            for (int nt = 0; nt < 8; nt++) {
#pragma unroll
                for (int e = 0; e < 2; e++) {
                    const int cl = nt * 8 + 2 * kq + e;
                    const int mv_ = mk[cl];
                    const int colg = k0 + cl;
                    if (mv_ && colg > qr0) act0 |= 1u << (nt * 2 + e);
                    if (mv_ && colg > qr1) act1 |= 1u << (nt * 2 + e);
                }
            }

            // ---- scale + masked tile max ----
            float t0 = -3.0e38f, t1 = -3.0e38f;
#pragma unroll
            for (int nt = 0; nt < 8; nt++) {
#pragma unroll
                for (int e = 0; e < 2; e++) {
                    float s0 = c[nt][e] * 0.125f;     c[nt][e] = s0;
                    float s1 = c[nt][2 + e] * 0.125f; c[nt][2 + e] = s1;
                    if ((act0 >> (nt * 2 + e)) & 1) t0 = fmaxf(t0, s0);
                    if ((act1 >> (nt * 2 + e)) & 1) t1 = fmaxf(t1, s1);
                }
            }
            t0 = fmaxf(t0, __shfl_xor_sync(0xffffffffu, t0, 1));
            t0 = fmaxf(t0, __shfl_xor_sync(0xffffffffu, t0, 2));
            t1 = fmaxf(t1, __shfl_xor_sync(0xffffffffu, t1, 1));
            t1 = fmaxf(t1, __shfl_xor_sync(0xffffffffu, t1, 2));

            const float mn0 = fmaxf(m0, t0), mn1 = fmaxf(m1, t1);
            const float cr0 = __expf(m0 - mn0), cr1 = __expf(m1 - mn1);
            m0 = mn0; m1 = mn1;

            // ---- p = exp or 0; row sums ----
            float rs0 = 0.f, rs1 = 0.f;
#pragma unroll
            for (int nt = 0; nt < 8; nt++) {
#pragma unroll
                for (int e = 0; e < 2; e++) {
                    float p0 = ((act0 >> (nt * 2 + e)) & 1)
                               ? __expf(c[nt][e] - mn0) : 0.f;
                    float p1 = ((act1 >> (nt * 2 + e)) & 1)
                               ? __expf(c[nt][2 + e] - mn1) : 0.f;
                    c[nt][e] = p0;     rs0 += p0;
                    c[nt][2 + e] = p1; rs1 += p1;
                }
            }
            rs0 += __shfl_xor_sync(0xffffffffu, rs0, 1);
            rs0 += __shfl_xor_sync(0xffffffffu, rs0, 2);
            rs1 += __shfl_xor_sync(0xffffffffu, rs1, 1);
            rs1 += __shfl_xor_sync(0xffffffffu, rs1, 2);
            l0 = l0 * cr0 + rs0;
            l1 = l1 * cr1 + rs1;

            // ---- rescale O, then O += P @ V (ldmatrix V fragments) ----
#pragma unroll
            for (int dt = 0; dt < 8; dt++) {
                o[dt][0] *= cr0; o[dt][1] *= cr0;
                o[dt][2] *= cr1; o[dt][3] *= cr1;
            }
#pragma unroll
            for (int kc = 0; kc < 4; kc++) {
                const int tA = 2 * kc, tB = 2 * kc + 1;
                uint32_t aPh[4];
                aPh[0] = pack_h2(c[tA][0], c[tA][1]);
                aPh[1] = pack_h2(c[tA][2], c[tA][3]);
                aPh[2] = pack_h2(c[tB][0], c[tB][1]);
                aPh[3] = pack_h2(c[tB][2], c[tB][3]);
#pragma unroll
                for (int dt = 0; dt < 8; dt++) {
                    const uint32_t aw = kbb +
                        (TW + (dt * 8 + alr) * WS + kc * 8 + alh * 4) * 4;
                    uint32_t bh2[2];
                    ldsm_x2(bh2, aw);
                    mma16816(o[dt], aPh, bh2);
                }
            }
            __syncthreads();
            buf ^= 1;
        }

        // ---- epilogue: write ctx fp16 ----
        const float inv0 = 1.0f / l0, inv1 = 1.0f / l1;
        const int fm0 = fm[b * SEQ + qr0];
        const int fm1 = fm[b * SEQ + qr1];
        const float* mvb = meanV + (size_t)(b * NHEADS + h) * DK;
#pragma unroll
        for (int dt = 0; dt < 8; dt++) {
            const int d = dt * 8 + 2 * kq;
            float2 mvv = *(const float2*)&mvb[d];
            float2 v0 = fm0 ? mvv : make_float2(o[dt][0] * inv0, o[dt][1] * inv0);
            float2 v1 = fm1 ? mvv : make_float2(o[dt][2] * inv1, o[dt][3] * inv1);
            const size_t p0 = (size_t)(b * SEQ + qr0) * DMODEL + h * DK + d;
            const size_t p1 = (size_t)(b * SEQ + qr1) * DMODEL + h * DK + d;
            *(uint32_t*)(ctxH + p0) = pack_h2(v0.x, v0.y);
            *(uint32_t*)(ctxH + p1) = pack_h2(v1.x, v1.y);
        }
    }
}

// ---------------------------------------------------------------------------
// LayerNorm: one CTA per token row (1024 elems, 256 threads)
// ---------------------------------------------------------------------------
__global__ void __launch_bounds__(256) ln_kernel(
    const float* __restrict__ x, const float* __restrict__ gamma,
    const float* __restrict__ beta, float* __restrict__ out)
{
    const int row = blockIdx.x;
    const int tid = threadIdx.x;
    const float* xr = x + (size_t)row * DMODEL;

    float4 v = *(const float4*)&xr[tid*4];
    float s  = v.x + v.y + v.z + v.w;
    float sq = v.x*v.x + v.y*v.y + v.z*v.z + v.w*v.w;
#pragma unroll
    for (int o = 16; o > 0; o >>= 1) {
        s  += __shfl_xor_sync(0xffffffffu, s,  o);
        sq += __shfl_xor_sync(0xffffffffu, sq, o);
    }
    __shared__ float ss[8], ssq[8], smu, sinv;
    const int wid = tid >> 5, lane = tid & 31;
    if (lane == 0) { ss[wid] = s; ssq[wid] = sq; }
    __syncthreads();
    if (tid == 0) {
        float S = 0.f, SQ = 0.f;
#pragma unroll
        for (int i = 0; i < 8; i++) { S += ss[i]; SQ += ssq[i]; }
        float mu = S * (1.0f/DMODEL);
        float var = SQ * (1.0f/DMODEL) - mu*mu;
        smu = mu;
        sinv = rsqrtf(var + 1e-5f);
    }
    __syncthreads();
    float mu = smu, inv = sinv;
    float4 g = *(const float4*)&gamma[tid*4];
    float4 be = *(const float4*)&beta[tid*4];
    float4 o;
    o.x = (v.x - mu) * inv * g.x + be.x;
    o.y = (v.y - mu) * inv * g.y + be.y;
    o.z = (v.z - mu) * inv * g.z + be.z;
    o.w = (v.w - mu) * inv * g.w + be.w;
    *(float4*)&out[(size_t)row*DMODEL + tid*4] = o;
}

// ---------------------------------------------------------------------------
extern "C" void kernel_launch(void* const* d_in, const int* in_sizes, int n_in,
                              void* d_out, int out_size)
{
    const float* inQ   = (const float*)d_in[0];
    const float* inK   = (const float*)d_in[1];
    const float* inV   = (const float*)d_in[2];
    const int*   amask = (const int*)  d_in[3];
    const float* W[4]  = { (const float*)d_in[4], (const float*)d_in[5],
                           (const float*)d_in[6], (const float*)d_in[7] };
    const float* gamma = (const float*)d_in[8];
    const float* beta  = (const float*)d_in[9];
    float* out = (float*)d_out;

    __half *inH, *WHp, *QH, *KH, *VTH, *ctxH;
    float *Vf, *tmp, *mv;
    int *fmp;
    cudaGetSymbolAddress((void**)&inH,  g_inH);
    cudaGetSymbolAddress((void**)&WHp,  g_WH);
    cudaGetSymbolAddress((void**)&QH,   g_QH);
    cudaGetSymbolAddress((void**)&KH,   g_KH);
    cudaGetSymbolAddress((void**)&Vf,   g_V);
    cudaGetSymbolAddress((void**)&VTH,  g_VTH);
    cudaGetSymbolAddress((void**)&ctxH, g_ctxH);
    cudaGetSymbolAddress((void**)&tmp,  g_tmp);
    cudaGetSymbolAddress((void**)&mv,   g_meanV);
    cudaGetSymbolAddress((void**)&fmp,  g_fm);

    cudaFuncSetAttribute(attn_mma_kernel,
                         cudaFuncAttributeMaxDynamicSharedMemorySize, ATT_SMEM);
    cudaFuncSetAttribute(qkv_gemm_kernel,
                         cudaFuncAttributeMaxDynamicSharedMemorySize, G_SMEM);
    cudaFuncSetAttribute(outproj_gemm_kernel,
                         cudaFuncAttributeMaxDynamicSharedMemorySize, G_SMEM);

    // ---- one-time fp16 conversions ----
    const float* ins[3] = { inQ, inK, inV };
    const int NIN = NTOK * DMODEL;         // 4M elements
    const int NW  = DMODEL * DMODEL;       // 1M elements
    SplitJobs sji{}, sjw{};
    for (int i = 0; i < 3; i++) {
        sji.x[i]  = (const float4*)ins[i];
        sji.hi[i] = (uint2*)(inH + (size_t)i * NIN);
    }
    sji.x[3] = sji.x[0]; sji.hi[3] = sji.hi[0];
    for (int i = 0; i < 4; i++) {
        sjw.x[i]  = (const float4*)W[i];
        sjw.hi[i] = (uint2*)(WHp + (size_t)i * NW);
    }
    split_hi_kernel<<<dim3(NIN/4/256, 3), 256>>>(sji);
    split_hi_kernel<<<dim3(NW/4/256, 4), 256>>>(sjw);

    // ---- fused QKV projection (grid z selects Q/K/V) ----
    QKVPtrs qp;
    for (int i = 0; i < 3; i++) {
        qp.ah[i] = inH + (size_t)i * NIN;
        qp.wh[i] = WHp + (size_t)i * NW;
    }
    qkv_gemm_kernel<<<dim3(DMODEL/128, NTOK/128, 3), 256, G_SMEM>>>(
        qp, QH, KH, Vf);

    vsplitT_kernel<<<dim3(SEQ/64, BH), 256>>>(Vf, VTH);
    fullmask_kernel<<<dim3(SEQ/1024, BATCH), 1024>>>(amask, fmp);
    meanv_kernel<<<BH, 256>>>(Vf, mv);

    attn_mma_kernel<<<dim3(8, NHEADS, BATCH), 256, ATT_SMEM>>>(
        QH, KH, VTH, amask, fmp, mv, ctxH);

    outproj_gemm_kernel<<<dim3(DMODEL/128, NTOK/128), 256, G_SMEM>>>(
        ctxH, WHp + (size_t)3 * NW, inQ, tmp);

    ln_kernel<<<NTOK, 256>>>(tmp, gamma, beta, out);
}